// round 10
// baseline (speedup 1.0000x reference)
#include <cuda_runtime.h>

// GTConv: out[c,r,e] = softmax(weight, axis=1)[c,r] * edge_w[r,e]
// Shapes: edge_w [R=8, E], weight [C=4, R=8].
// Output layout: out (C*R*E floats) followed by Filter (C*R floats).
//
// Config: VPT=2 float4s/thread, TPB=256, batched __ldcs loads (evict-first:
// reads are single-use), interleaved DEFAULT-policy stores (evict-normal:
// maximize dirty-write retention in the 126MB L2 at kernel end, minimizing
// DRAM writeback inside the timed window), fused Filter-tail write.

#define GT_R 8
#define GT_C 4
#define VPT 2   // float4s per thread

__global__ void gtconv_vec4x2_kernel(const float4* __restrict__ ew,
                                     const float*  __restrict__ weight,
                                     float4* __restrict__ out,
                                     float*  __restrict__ out_tail, // may be null
                                     int e4)   // E/4
{
    __shared__ float F[GT_C][GT_R];
    const int tid = threadIdx.x;
    if (tid < GT_C) {
        float w[GT_R];
        float m = -3.402823e38f;
#pragma unroll
        for (int r = 0; r < GT_R; ++r) { w[r] = weight[tid * GT_R + r]; m = fmaxf(m, w[r]); }
        float s = 0.f;
#pragma unroll
        for (int r = 0; r < GT_R; ++r) { w[r] = __expf(w[r] - m); s += w[r]; }
        const float inv = 1.0f / s;
#pragma unroll
        for (int r = 0; r < GT_R; ++r) F[tid][r] = w[r] * inv;
        if (out_tail != nullptr && blockIdx.x == 0 && blockIdx.y == 0) {
#pragma unroll
            for (int r = 0; r < GT_R; ++r) out_tail[tid * GT_R + r] = w[r] * inv;
        }
    }
    __syncthreads();

    const int r = blockIdx.y;
    const int bd = blockDim.x;
    const long long base = (long long)blockIdx.x * (bd * VPT) + tid;
    const long long re_total = (long long)GT_R * e4;   // float4s per channel
    const long long rbase = (long long)r * e4;

    const float f0 = F[0][r], f1 = F[1][r], f2 = F[2][r], f3 = F[3][r];

    if (base + (VPT - 1) * (long long)bd < e4) {
        // Fast path: batch the VPT loads first (MLP=2), then 4*VPT stores
        // interleaved across channel streams (measured-best order).
        float4 v[VPT];
        long long idx[VPT];
#pragma unroll
        for (int i = 0; i < VPT; ++i) {
            idx[i] = rbase + base + (long long)i * bd;
            v[i] = __ldcs(&ew[idx[i]]);
        }
#pragma unroll
        for (int i = 0; i < VPT; ++i) {
            float4 o;
            o.x = v[i].x * f0; o.y = v[i].y * f0; o.z = v[i].z * f0; o.w = v[i].w * f0;
            out[0 * re_total + idx[i]] = o;
            o.x = v[i].x * f1; o.y = v[i].y * f1; o.z = v[i].z * f1; o.w = v[i].w * f1;
            out[1 * re_total + idx[i]] = o;
            o.x = v[i].x * f2; o.y = v[i].y * f2; o.z = v[i].z * f2; o.w = v[i].w * f2;
            out[2 * re_total + idx[i]] = o;
            o.x = v[i].x * f3; o.y = v[i].y * f3; o.z = v[i].z * f3; o.w = v[i].w * f3;
            out[3 * re_total + idx[i]] = o;
        }
    } else {
        // Tail path: per-element guard.
#pragma unroll
        for (int i = 0; i < VPT; ++i) {
            const long long e = base + (long long)i * bd;
            if (e >= e4) break;
            const long long idx = rbase + e;
            const float4 v = __ldcs(&ew[idx]);
            float4 o;
            o.x = v.x * f0; o.y = v.y * f0; o.z = v.z * f0; o.w = v.w * f0;
            out[0 * re_total + idx] = o;
            o.x = v.x * f1; o.y = v.y * f1; o.z = v.z * f1; o.w = v.w * f1;
            out[1 * re_total + idx] = o;
            o.x = v.x * f2; o.y = v.y * f2; o.z = v.z * f2; o.w = v.w * f2;
            out[2 * re_total + idx] = o;
            o.x = v.x * f3; o.y = v.y * f3; o.z = v.z * f3; o.w = v.w * f3;
            out[3 * re_total + idx] = o;
        }
    }
}

// Scalar fallback if E is not divisible by 4 (also fused tail).
__global__ void gtconv_scalar_kernel(const float* __restrict__ ew,
                                     const float* __restrict__ weight,
                                     float* __restrict__ out,
                                     float* __restrict__ out_tail,
                                     long long E)
{
    __shared__ float F[GT_C][GT_R];
    const int tid = threadIdx.x;
    if (tid < GT_C) {
        float w[GT_R];
        float m = -3.402823e38f;
#pragma unroll
        for (int r = 0; r < GT_R; ++r) { w[r] = weight[tid * GT_R + r]; m = fmaxf(m, w[r]); }
        float s = 0.f;
#pragma unroll
        for (int r = 0; r < GT_R; ++r) { w[r] = __expf(w[r] - m); s += w[r]; }
        const float inv = 1.0f / s;
#pragma unroll
        for (int r = 0; r < GT_R; ++r) F[tid][r] = w[r] * inv;
        if (out_tail != nullptr && blockIdx.x == 0 && blockIdx.y == 0) {
#pragma unroll
            for (int r = 0; r < GT_R; ++r) out_tail[tid * GT_R + r] = w[r] * inv;
        }
    }
    __syncthreads();

    const int r = blockIdx.y;
    const long long e = (long long)blockIdx.x * blockDim.x + tid;
    if (e >= E) return;

    const long long re_total = (long long)GT_R * E;
    const long long idx = (long long)r * E + e;
    const float v = __ldcs(&ew[idx]);
#pragma unroll
    for (int c = 0; c < GT_C; ++c)
        out[(long long)c * re_total + idx] = v * F[c][r];
}

extern "C" void kernel_launch(void* const* d_in, const int* in_sizes, int n_in,
                              void* d_out, int out_size)
{
    // Identify inputs: edge_w is the big array (R*E), weight is C*R = 32.
    const float* edge_w = (const float*)d_in[0];
    const float* weight = (const float*)d_in[1];
    long long n_ew = in_sizes[0];
    if (n_in >= 2 && in_sizes[1] > in_sizes[0]) {
        edge_w = (const float*)d_in[1];
        weight = (const float*)d_in[0];
        n_ew = in_sizes[1];
    }

    const long long E = n_ew / GT_R;
    float* out = (float*)d_out;

    const long long main_elems = (long long)GT_C * GT_R * E;
    float* out_tail =
        ((long long)out_size >= main_elems + GT_C * GT_R) ? (out + main_elems) : nullptr;

    const int threads = 256;
    if ((E & 3LL) == 0) {
        const int e4 = (int)(E / 4);
        const int per_block = threads * VPT;
        dim3 grid((unsigned)((e4 + per_block - 1) / per_block), GT_R, 1);
        gtconv_vec4x2_kernel<<<grid, threads>>>(
            (const float4*)edge_w, weight, (float4*)out, out_tail, e4);
    } else {
        dim3 grid((unsigned)((E + threads - 1) / threads), GT_R, 1);
        gtconv_scalar_kernel<<<grid, threads>>>(edge_w, weight, out, out_tail, E);
    }
}

// round 11
// speedup vs baseline: 1.0036x; 1.0036x over previous
#include <cuda_runtime.h>

// GTConv: out[c,r,e] = softmax(weight, axis=1)[c,r] * edge_w[r,e]
// Shapes: edge_w [R=8, E], weight [C=4, R=8].
// Output layout: out (C*R*E floats) followed by Filter (C*R floats).
//
// FINAL (converged over 10 rounds): VPT=2 float4s/thread, TPB=256, batched
// __ldcs loads then interleaved __stcs stores across the 4 channel streams,
// fused Filter-tail write. Main kernel ~47.4us = ~6.8 TB/s app bandwidth,
// the achieved HBM3e ceiling for this 1:4 read:write mix. Measured slower:
// VPT{1,4}, TPB512, int32 indexing, channel-major stores, CTA channel
// fan-out + L2 reuse, default store policy.

#define GT_R 8
#define GT_C 4
#define VPT 2   // float4s per thread

__global__ void gtconv_vec4x2_kernel(const float4* __restrict__ ew,
                                     const float*  __restrict__ weight,
                                     float4* __restrict__ out,
                                     float*  __restrict__ out_tail, // may be null
                                     int e4)   // E/4
{
    __shared__ float F[GT_C][GT_R];
    const int tid = threadIdx.x;
    if (tid < GT_C) {
        float w[GT_R];
        float m = -3.402823e38f;
#pragma unroll
        for (int r = 0; r < GT_R; ++r) { w[r] = weight[tid * GT_R + r]; m = fmaxf(m, w[r]); }
        float s = 0.f;
#pragma unroll
        for (int r = 0; r < GT_R; ++r) { w[r] = __expf(w[r] - m); s += w[r]; }
        const float inv = 1.0f / s;
#pragma unroll
        for (int r = 0; r < GT_R; ++r) F[tid][r] = w[r] * inv;
        if (out_tail != nullptr && blockIdx.x == 0 && blockIdx.y == 0) {
#pragma unroll
            for (int r = 0; r < GT_R; ++r) out_tail[tid * GT_R + r] = w[r] * inv;
        }
    }
    __syncthreads();

    const int r = blockIdx.y;
    const int bd = blockDim.x;
    const long long base = (long long)blockIdx.x * (bd * VPT) + tid;
    const long long re_total = (long long)GT_R * e4;   // float4s per channel
    const long long rbase = (long long)r * e4;

    const float f0 = F[0][r], f1 = F[1][r], f2 = F[2][r], f3 = F[3][r];

    if (base + (VPT - 1) * (long long)bd < e4) {
        // Fast path: batch the VPT loads first (MLP=2), then 4*VPT stores
        // interleaved across channel streams (measured-best order).
        float4 v[VPT];
        long long idx[VPT];
#pragma unroll
        for (int i = 0; i < VPT; ++i) {
            idx[i] = rbase + base + (long long)i * bd;
            v[i] = __ldcs(&ew[idx[i]]);
        }
#pragma unroll
        for (int i = 0; i < VPT; ++i) {
            float4 o;
            o.x = v[i].x * f0; o.y = v[i].y * f0; o.z = v[i].z * f0; o.w = v[i].w * f0;
            __stcs(&out[0 * re_total + idx[i]], o);
            o.x = v[i].x * f1; o.y = v[i].y * f1; o.z = v[i].z * f1; o.w = v[i].w * f1;
            __stcs(&out[1 * re_total + idx[i]], o);
            o.x = v[i].x * f2; o.y = v[i].y * f2; o.z = v[i].z * f2; o.w = v[i].w * f2;
            __stcs(&out[2 * re_total + idx[i]], o);
            o.x = v[i].x * f3; o.y = v[i].y * f3; o.z = v[i].z * f3; o.w = v[i].w * f3;
            __stcs(&out[3 * re_total + idx[i]], o);
        }
    } else {
        // Tail path: per-element guard.
#pragma unroll
        for (int i = 0; i < VPT; ++i) {
            const long long e = base + (long long)i * bd;
            if (e >= e4) break;
            const long long idx = rbase + e;
            const float4 v = __ldcs(&ew[idx]);
            float4 o;
            o.x = v.x * f0; o.y = v.y * f0; o.z = v.z * f0; o.w = v.w * f0;
            __stcs(&out[0 * re_total + idx], o);
            o.x = v.x * f1; o.y = v.y * f1; o.z = v.z * f1; o.w = v.w * f1;
            __stcs(&out[1 * re_total + idx], o);
            o.x = v.x * f2; o.y = v.y * f2; o.z = v.z * f2; o.w = v.w * f2;
            __stcs(&out[2 * re_total + idx], o);
            o.x = v.x * f3; o.y = v.y * f3; o.z = v.z * f3; o.w = v.w * f3;
            __stcs(&out[3 * re_total + idx], o);
        }
    }
}

// Scalar fallback if E is not divisible by 4 (also fused tail).
__global__ void gtconv_scalar_kernel(const float* __restrict__ ew,
                                     const float* __restrict__ weight,
                                     float* __restrict__ out,
                                     float* __restrict__ out_tail,
                                     long long E)
{
    __shared__ float F[GT_C][GT_R];
    const int tid = threadIdx.x;
    if (tid < GT_C) {
        float w[GT_R];
        float m = -3.402823e38f;
#pragma unroll
        for (int r = 0; r < GT_R; ++r) { w[r] = weight[tid * GT_R + r]; m = fmaxf(m, w[r]); }
        float s = 0.f;
#pragma unroll
        for (int r = 0; r < GT_R; ++r) { w[r] = __expf(w[r] - m); s += w[r]; }
        const float inv = 1.0f / s;
#pragma unroll
        for (int r = 0; r < GT_R; ++r) F[tid][r] = w[r] * inv;
        if (out_tail != nullptr && blockIdx.x == 0 && blockIdx.y == 0) {
#pragma unroll
            for (int r = 0; r < GT_R; ++r) out_tail[tid * GT_R + r] = w[r] * inv;
        }
    }
    __syncthreads();

    const int r = blockIdx.y;
    const long long e = (long long)blockIdx.x * blockDim.x + tid;
    if (e >= E) return;

    const long long re_total = (long long)GT_R * E;
    const long long idx = (long long)r * E + e;
    const float v = __ldcs(&ew[idx]);
#pragma unroll
    for (int c = 0; c < GT_C; ++c)
        __stcs(&out[(long long)c * re_total + idx], v * F[c][r]);
}

extern "C" void kernel_launch(void* const* d_in, const int* in_sizes, int n_in,
                              void* d_out, int out_size)
{
    // Identify inputs: edge_w is the big array (R*E), weight is C*R = 32.
    const float* edge_w = (const float*)d_in[0];
    const float* weight = (const float*)d_in[1];
    long long n_ew = in_sizes[0];
    if (n_in >= 2 && in_sizes[1] > in_sizes[0]) {
        edge_w = (const float*)d_in[1];
        weight = (const float*)d_in[0];
        n_ew = in_sizes[1];
    }

    const long long E = n_ew / GT_R;
    float* out = (float*)d_out;

    const long long main_elems = (long long)GT_C * GT_R * E;
    float* out_tail =
        ((long long)out_size >= main_elems + GT_C * GT_R) ? (out + main_elems) : nullptr;

    const int threads = 256;
    if ((E & 3LL) == 0) {
        const int e4 = (int)(E / 4);
        const int per_block = threads * VPT;
        dim3 grid((unsigned)((e4 + per_block - 1) / per_block), GT_R, 1);
        gtconv_vec4x2_kernel<<<grid, threads>>>(
            (const float4*)edge_w, weight, (float4*)out, out_tail, e4);
    } else {
        dim3 grid((unsigned)((E + threads - 1) / threads), GT_R, 1);
        gtconv_scalar_kernel<<<grid, threads>>>(edge_w, weight, out, out_tail, E);
    }
}

// round 12
// speedup vs baseline: 1.0260x; 1.0223x over previous
#include <cuda_runtime.h>

// GTConv: out[c,r,e] = softmax(weight, axis=1)[c,r] * edge_w[r,e]
// Shapes: edge_w [R=8, E], weight [C=4, R=8].
// Output layout: out (C*R*E floats) followed by Filter (C*R floats).
//
// FINAL (converged, 11 rounds): VPT=2 float4s/thread, TPB=256, batched
// __ldcs loads then interleaved __stcs stores across the 4 channel streams,
// fused Filter-tail write. Main kernel ~47.4us = ~6.8 TB/s app bandwidth,
// at the B300 HBM/LTS ceiling for this 1:4 read:write streaming mix.
// Measured slower or neutral: VPT{1,4}, TPB512, int32 indexing,
// channel-major stores, CTA channel fan-out + L2 reuse, default store
// policy, per-thread softmax.

#define GT_R 8
#define GT_C 4
#define VPT 2   // float4s per thread

__global__ void gtconv_vec4x2_kernel(const float4* __restrict__ ew,
                                     const float*  __restrict__ weight,
                                     float4* __restrict__ out,
                                     float*  __restrict__ out_tail, // may be null
                                     int e4)   // E/4
{
    __shared__ float F[GT_C][GT_R];
    const int tid = threadIdx.x;
    if (tid < GT_C) {
        float w[GT_R];
        float m = -3.402823e38f;
#pragma unroll
        for (int r = 0; r < GT_R; ++r) { w[r] = weight[tid * GT_R + r]; m = fmaxf(m, w[r]); }
        float s = 0.f;
#pragma unroll
        for (int r = 0; r < GT_R; ++r) { w[r] = __expf(w[r] - m); s += w[r]; }
        const float inv = 1.0f / s;
#pragma unroll
        for (int r = 0; r < GT_R; ++r) F[tid][r] = w[r] * inv;
        if (out_tail != nullptr && blockIdx.x == 0 && blockIdx.y == 0) {
#pragma unroll
            for (int r = 0; r < GT_R; ++r) out_tail[tid * GT_R + r] = w[r] * inv;
        }
    }
    __syncthreads();

    const int r = blockIdx.y;
    const int bd = blockDim.x;
    const long long base = (long long)blockIdx.x * (bd * VPT) + tid;
    const long long re_total = (long long)GT_R * e4;   // float4s per channel
    const long long rbase = (long long)r * e4;

    const float f0 = F[0][r], f1 = F[1][r], f2 = F[2][r], f3 = F[3][r];

    if (base + (VPT - 1) * (long long)bd < e4) {
        // Fast path: batch the VPT loads first (MLP=2), then 4*VPT stores
        // interleaved across channel streams (measured-best order).
        float4 v[VPT];
        long long idx[VPT];
#pragma unroll
        for (int i = 0; i < VPT; ++i) {
            idx[i] = rbase + base + (long long)i * bd;
            v[i] = __ldcs(&ew[idx[i]]);
        }
#pragma unroll
        for (int i = 0; i < VPT; ++i) {
            float4 o;
            o.x = v[i].x * f0; o.y = v[i].y * f0; o.z = v[i].z * f0; o.w = v[i].w * f0;
            __stcs(&out[0 * re_total + idx[i]], o);
            o.x = v[i].x * f1; o.y = v[i].y * f1; o.z = v[i].z * f1; o.w = v[i].w * f1;
            __stcs(&out[1 * re_total + idx[i]], o);
            o.x = v[i].x * f2; o.y = v[i].y * f2; o.z = v[i].z * f2; o.w = v[i].w * f2;
            __stcs(&out[2 * re_total + idx[i]], o);
            o.x = v[i].x * f3; o.y = v[i].y * f3; o.z = v[i].z * f3; o.w = v[i].w * f3;
            __stcs(&out[3 * re_total + idx[i]], o);
        }
    } else {
        // Tail path: per-element guard.
#pragma unroll
        for (int i = 0; i < VPT; ++i) {
            const long long e = base + (long long)i * bd;
            if (e >= e4) break;
            const long long idx = rbase + e;
            const float4 v = __ldcs(&ew[idx]);
            float4 o;
            o.x = v.x * f0; o.y = v.y * f0; o.z = v.z * f0; o.w = v.w * f0;
            __stcs(&out[0 * re_total + idx], o);
            o.x = v.x * f1; o.y = v.y * f1; o.z = v.z * f1; o.w = v.w * f1;
            __stcs(&out[1 * re_total + idx], o);
            o.x = v.x * f2; o.y = v.y * f2; o.z = v.z * f2; o.w = v.w * f2;
            __stcs(&out[2 * re_total + idx], o);
            o.x = v.x * f3; o.y = v.y * f3; o.z = v.z * f3; o.w = v.w * f3;
            __stcs(&out[3 * re_total + idx], o);
        }
    }
}

// Scalar fallback if E is not divisible by 4 (also fused tail).
__global__ void gtconv_scalar_kernel(const float* __restrict__ ew,
                                     const float* __restrict__ weight,
                                     float* __restrict__ out,
                                     float* __restrict__ out_tail,
                                     long long E)
{
    __shared__ float F[GT_C][GT_R];
    const int tid = threadIdx.x;
    if (tid < GT_C) {
        float w[GT_R];
        float m = -3.402823e38f;
#pragma unroll
        for (int r = 0; r < GT_R; ++r) { w[r] = weight[tid * GT_R + r]; m = fmaxf(m, w[r]); }
        float s = 0.f;
#pragma unroll
        for (int r = 0; r < GT_R; ++r) { w[r] = __expf(w[r] - m); s += w[r]; }
        const float inv = 1.0f / s;
#pragma unroll
        for (int r = 0; r < GT_R; ++r) F[tid][r] = w[r] * inv;
        if (out_tail != nullptr && blockIdx.x == 0 && blockIdx.y == 0) {
#pragma unroll
            for (int r = 0; r < GT_R; ++r) out_tail[tid * GT_R + r] = w[r] * inv;
        }
    }
    __syncthreads();

    const int r = blockIdx.y;
    const long long e = (long long)blockIdx.x * blockDim.x + tid;
    if (e >= E) return;

    const long long re_total = (long long)GT_R * E;
    const long long idx = (long long)r * E + e;
    const float v = __ldcs(&ew[idx]);
#pragma unroll
    for (int c = 0; c < GT_C; ++c)
        __stcs(&out[(long long)c * re_total + idx], v * F[c][r]);
}

extern "C" void kernel_launch(void* const* d_in, const int* in_sizes, int n_in,
                              void* d_out, int out_size)
{
    // Identify inputs: edge_w is the big array (R*E), weight is C*R = 32.
    const float* edge_w = (const float*)d_in[0];
    const float* weight = (const float*)d_in[1];
    long long n_ew = in_sizes[0];
    if (n_in >= 2 && in_sizes[1] > in_sizes[0]) {
        edge_w = (const float*)d_in[1];
        weight = (const float*)d_in[0];
        n_ew = in_sizes[1];
    }

    const long long E = n_ew / GT_R;
    float* out = (float*)d_out;

    const long long main_elems = (long long)GT_C * GT_R * E;
    float* out_tail =
        ((long long)out_size >= main_elems + GT_C * GT_R) ? (out + main_elems) : nullptr;

    const int threads = 256;
    if ((E & 3LL) == 0) {
        const int e4 = (int)(E / 4);
        const int per_block = threads * VPT;
        dim3 grid((unsigned)((e4 + per_block - 1) / per_block), GT_R, 1);
        gtconv_vec4x2_kernel<<<grid, threads>>>(
            (const float4*)edge_w, weight, (float4*)out, out_tail, e4);
    } else {
        dim3 grid((unsigned)((E + threads - 1) / threads), GT_R, 1);
        gtconv_scalar_kernel<<<grid, threads>>>(edge_w, weight, out, out_tail, E);
    }
}